// round 17
// baseline (speedup 1.0000x reference)
#include <cuda_runtime.h>
#include <mma.h>
using namespace nvcuda;

#define NAB 20000
#define NAG 20000
#define NTOT 40000
#define FDIM 256
#define EAB 320000
#define EAG 320000
#define ED 640000
#define ETOT (EAB + EAG + ED)
#define EPSV 1e-5f
#define MPAD 40192
#define CSRN (3 * NTOT)
#define SCAN_BLOCKS ((CSRN + 1023) / 1024)
#define ALD 20
#define BLD 132
#define RPAD 64  // row padding so unpredicated GEMM A-loads stay in-bounds

// ---------------- scratch (device globals; no allocs) ----------------
__device__ float g_h[(NTOT + RPAD) * FDIM];   // 0
__device__ float g_xa[(NTOT + RPAD) * FDIM];  // 1
__device__ float g_xb[(NTOT + RPAD) * FDIM];  // 2
__device__ float g_tmp[MPAD * FDIM];          // 3
__device__ float g_deg[NTOT];
__device__ float g_es[NTOT];
__device__ float g_ed[NTOT];
__device__ float g_csum[4][FDIM];
__device__ float g_csq[4][FDIM];
__device__ int g_cnt[CSRN];
__device__ int g_rowg[CSRN + 1];
__device__ int g_bsum[SCAN_BLOCKS];
__device__ int g_srt[ETOT];

__device__ __forceinline__ float* BUF(int which) {
    switch (which) {
        case 0: return g_h;
        case 1: return g_xa;
        case 2: return g_xb;
        default: return g_tmp;
    }
}

__device__ __forceinline__ float lrelu(float x) { return x > 0.f ? x : 0.2f * x; }

// ---------------- batched CSR build ----------------
__global__ void k_zero_csr() {
    int i = blockIdx.x * blockDim.x + threadIdx.x;
    if (i < CSRN) g_cnt[i] = 0;
}
__global__ void k_hist_all(const int* __restrict__ dab, const int* __restrict__ dag,
                           const int* __restrict__ dd) {
    int e = blockIdx.x * blockDim.x + threadIdx.x;
    if (e < EAB) atomicAdd(&g_cnt[0 * NTOT + dab[e]], 1);
    else if (e < EAB + EAG) atomicAdd(&g_cnt[1 * NTOT + dag[e - EAB]], 1);
    else if (e < ETOT) atomicAdd(&g_cnt[2 * NTOT + dd[e - EAB - EAG]], 1);
}
__global__ void k_scan1() {
    __shared__ int wsum[32];
    int gi = blockIdx.x * 1024 + threadIdx.x;
    int v = (gi < CSRN) ? g_cnt[gi] : 0;
    if (gi < NAB) g_deg[gi] = rsqrtf((float)(v + 1));
    else if (gi >= NTOT && gi < NTOT + NAG) g_deg[NAB + gi - NTOT] = rsqrtf((float)(v + 1));
    if (gi < 4 * FDIM) {  // fused zero of BN stat slots 0-3
        ((float*)g_csum)[gi] = 0.f;
        ((float*)g_csq)[gi] = 0.f;
    }
    int lane = threadIdx.x & 31, wid = threadIdx.x >> 5;
    int inc = v;
#pragma unroll
    for (int o = 1; o < 32; o <<= 1) {
        int u = __shfl_up_sync(0xFFFFFFFFu, inc, o);
        if (lane >= o) inc += u;
    }
    if (lane == 31) wsum[wid] = inc;
    __syncthreads();
    if (wid == 0) {
        int w = wsum[lane];
#pragma unroll
        for (int o = 1; o < 32; o <<= 1) {
            int u = __shfl_up_sync(0xFFFFFFFFu, w, o);
            if (lane >= o) w += u;
        }
        wsum[lane] = w;
    }
    __syncthreads();
    int ex = inc - v + (wid ? wsum[wid - 1] : 0);
    if (gi < CSRN) g_rowg[gi] = ex;
    if (threadIdx.x == 1023) g_bsum[blockIdx.x] = ex + v;
}
__global__ void k_scan2() {
    __shared__ int ws[4];
    int t = threadIdx.x;
    int lane = t & 31, wid = t >> 5;
    int v = (t < SCAN_BLOCKS) ? g_bsum[t] : 0;
    int inc = v;
#pragma unroll
    for (int o = 1; o < 32; o <<= 1) {
        int u = __shfl_up_sync(0xFFFFFFFFu, inc, o);
        if (lane >= o) inc += u;
    }
    if (lane == 31) ws[wid] = inc;
    __syncthreads();
    int add = 0;
    for (int i = 0; i < wid; i++) add += ws[i];
    if (t < SCAN_BLOCKS) g_bsum[t] = inc - v + add;
}
__global__ void k_scan3() {
    int gi = blockIdx.x * 1024 + threadIdx.x;
    if (gi < CSRN) {
        int r = g_rowg[gi] + g_bsum[blockIdx.x];
        g_rowg[gi] = r;
        g_cnt[gi] = r;
    }
    if (gi == 0) g_rowg[CSRN] = ETOT;
}
__global__ void k_fill_all(const int* __restrict__ eab, const int* __restrict__ eag,
                           const int* __restrict__ ed) {
    int e = blockIdx.x * blockDim.x + threadIdx.x;
    int g, le;
    const int* src;
    const int* dst;
    if (e < EAB) { g = 0; le = e; src = eab; dst = eab + EAB; }
    else if (e < EAB + EAG) { g = 1; le = e - EAB; src = eag; dst = eag + EAG; }
    else if (e < ETOT) { g = 2; le = e - EAB - EAG; src = ed; dst = ed + ED; }
    else return;
    int d = dst[le];
    int pos = atomicAdd(&g_cnt[g * NTOT + d], 1);
    g_srt[pos] = src[le];
}

// ---------------- TF32 wmma GEMM core ----------------
// CHK=1: predicated A loads (external input, exact M). CHK=0: unconditional
// (A is a padded device-global; over-read <=64 rows stays in owned memory).
template <int CHK>
__device__ __forceinline__ void gemm_body(const float* __restrict__ A,
                                          const float* __restrict__ B, int M, int outrow0,
                                          int by, int bx) {
    __shared__ alignas(16) float As[2][128][ALD];
    __shared__ alignas(16) float Bs[2][16][BLD];
    int t = threadIdx.x;
    int wid = t >> 5;
    int wr = wid >> 2;
    int wc = wid & 3;
    int brow0 = by * 128;
    int bcol0 = bx * 128;

    wmma::fragment<wmma::accumulator, 16, 16, 8, float> c[4][2];
#pragma unroll
    for (int i = 0; i < 4; i++)
#pragma unroll
        for (int j = 0; j < 2; j++) wmma::fill_fragment(c[i][j], 0.0f);

    int af0 = t * 2, af1 = t * 2 + 1;
    int ar0 = af0 >> 2, ac0 = (af0 & 3) << 2;
    int ar1 = af1 >> 2, ac1 = (af1 & 3) << 2;
    int br0 = af0 >> 5, bc0 = (af0 & 31) << 2;
    int br1 = af1 >> 5, bc1 = (af1 & 31) << 2;

#define CVT4(v)                                  \
    do {                                         \
        (v).x = wmma::__float_to_tf32((v).x);    \
        (v).y = wmma::__float_to_tf32((v).y);    \
        (v).z = wmma::__float_to_tf32((v).z);    \
        (v).w = wmma::__float_to_tf32((v).w);    \
    } while (0)

    {
        float4 z = make_float4(0.f, 0.f, 0.f, 0.f);
        float4 a0v = (!CHK || brow0 + ar0 < M) ? *(const float4*)(A + (brow0 + ar0) * 256 + ac0) : z;
        float4 a1v = (!CHK || brow0 + ar1 < M) ? *(const float4*)(A + (brow0 + ar1) * 256 + ac1) : z;
        float4 b0v = *(const float4*)(B + br0 * 256 + bcol0 + bc0);
        float4 b1v = *(const float4*)(B + br1 * 256 + bcol0 + bc1);
        CVT4(a0v); CVT4(a1v); CVT4(b0v); CVT4(b1v);
        *(float4*)&As[0][ar0][ac0] = a0v;
        *(float4*)&As[0][ar1][ac1] = a1v;
        *(float4*)&Bs[0][br0][bc0] = b0v;
        *(float4*)&Bs[0][br1][bc1] = b1v;
    }
    __syncthreads();
    int cur = 0;
    for (int k0 = 16; k0 <= 256; k0 += 16) {
        float4 a0v, a1v, b0v, b1v;
        if (k0 < 256) {
            float4 z = make_float4(0.f, 0.f, 0.f, 0.f);
            a0v = (!CHK || brow0 + ar0 < M) ? *(const float4*)(A + (brow0 + ar0) * 256 + k0 + ac0) : z;
            a1v = (!CHK || brow0 + ar1 < M) ? *(const float4*)(A + (brow0 + ar1) * 256 + k0 + ac1) : z;
            b0v = *(const float4*)(B + (k0 + br0) * 256 + bcol0 + bc0);
            b1v = *(const float4*)(B + (k0 + br1) * 256 + bcol0 + bc1);
        }
#pragma unroll
        for (int kk = 0; kk < 16; kk += 8) {
            wmma::fragment<wmma::matrix_a, 16, 16, 8, wmma::precision::tf32, wmma::row_major> a[4];
            wmma::fragment<wmma::matrix_b, 16, 16, 8, wmma::precision::tf32, wmma::row_major> b[2];
#pragma unroll
            for (int i = 0; i < 4; i++)
                wmma::load_matrix_sync(a[i], &As[cur][wr * 64 + i * 16][kk], ALD);
#pragma unroll
            for (int j = 0; j < 2; j++)
                wmma::load_matrix_sync(b[j], &Bs[cur][kk][wc * 32 + j * 16], BLD);
#pragma unroll
            for (int i = 0; i < 4; i++)
#pragma unroll
                for (int j = 0; j < 2; j++) wmma::mma_sync(c[i][j], a[i], b[j], c[i][j]);
        }
        if (k0 < 256) {
            int nxt = cur ^ 1;
            CVT4(a0v); CVT4(a1v); CVT4(b0v); CVT4(b1v);
            *(float4*)&As[nxt][ar0][ac0] = a0v;
            *(float4*)&As[nxt][ar1][ac1] = a1v;
            *(float4*)&Bs[nxt][br0][bc0] = b0v;
            *(float4*)&Bs[nxt][br1][bc1] = b1v;
            __syncthreads();
            cur = nxt;
        }
    }
#pragma unroll
    for (int i = 0; i < 4; i++)
#pragma unroll
        for (int j = 0; j < 2; j++)
            wmma::store_matrix_sync(
                g_tmp + (long)(outrow0 + brow0 + wr * 64 + i * 16) * 256 + bcol0 + wc * 32 +
                    j * 16,
                c[i][j], 256, wmma::mem_row_major);
#undef CVT4
}

__global__ void __launch_bounds__(256, 2)
k_gemm(const float* __restrict__ Aext, int awhich, const float* __restrict__ B, int M) {
    if (awhich < 0) gemm_body<1>(Aext, B, M, 0, blockIdx.y, blockIdx.x);
    else gemm_body<0>(BUF(awhich), B, M, 0, blockIdx.y, blockIdx.x);
}
__global__ void __launch_bounds__(256, 2)
k_gemm2(const float* __restrict__ x_ab, const float* __restrict__ W_ab,
        const float* __restrict__ x_ag, const float* __restrict__ W_ag) {
    if (blockIdx.z == 0) gemm_body<1>(x_ab, W_ab, NAB, 0, blockIdx.y, blockIdx.x);
    else gemm_body<1>(x_ag, W_ag, NAG, NAB, blockIdx.y, blockIdx.x);
}

// ---------------- merged GCN pull: warp per dst ----------------
__global__ void k_gcn_pull2(const float* __restrict__ b_ab, const float* __restrict__ b_ag) {
    int w = (blockIdx.x * blockDim.x + threadIdx.x) >> 5;
    int lane = threadIdx.x & 31;
    if (w >= NTOT) return;
    int g, local, tmprow;
    const float* b;
    if (w < NAB) { g = 0; local = w; tmprow = 0; b = b_ab; }
    else { g = 1; local = w - NAB; tmprow = NAB; b = b_ag; }
    int rb = g * NTOT;
    int r0 = g_rowg[rb + local], r1 = g_rowg[rb + local + 1];
    float dd = g_deg[w];
    const float4* hp = (const float4*)(g_tmp + (long)(tmprow + local) * FDIM);
    float4 a0 = hp[lane];
    float4 a1 = hp[lane + 32];
    float sc = dd * dd;
    a0.x *= sc; a0.y *= sc; a0.z *= sc; a0.w *= sc;
    a1.x *= sc; a1.y *= sc; a1.z *= sc; a1.w *= sc;
    int degbase = (g == 0) ? 0 : NAB;
    for (int j = r0; j < r1; j++) {
        int s = g_srt[j];
        float nm = g_deg[degbase + s] * dd;
        const float4* sp = (const float4*)(g_tmp + (long)(tmprow + s) * FDIM);
        float4 v0 = sp[lane];
        float4 v1 = sp[lane + 32];
        a0.x += v0.x * nm; a0.y += v0.y * nm; a0.z += v0.z * nm; a0.w += v0.w * nm;
        a1.x += v1.x * nm; a1.y += v1.y * nm; a1.z += v1.z * nm; a1.w += v1.w * nm;
    }
    float4 b0 = *((const float4*)b + lane);
    float4 b1 = *((const float4*)b + lane + 32);
    a0.x += b0.x; a0.y += b0.y; a0.z += b0.z; a0.w += b0.w;
    a1.x += b1.x; a1.y += b1.y; a1.z += b1.z; a1.w += b1.w;
    float4* op = (float4*)(g_h + (long)w * FDIM);
    op[lane] = a0;
    op[lane + 32] = a1;
}

// ---------------- BN stats (float4 versions) ----------------
// generic: accumulate stats of x[nrows] into slot; 256 blocks per group
__device__ __forceinline__ void colstats_body(const float* __restrict__ xbase, int nrows,
                                              int slot, int blk) {
    const float4* x = (const float4*)xbase;
    int c4 = threadIdx.x & 63;    // float4 column
    int rsub = threadIdx.x >> 6;  // 0..3
    float s0 = 0, s1 = 0, s2 = 0, s3 = 0, q0 = 0, q1 = 0, q2 = 0, q3 = 0;
    for (int r = blk * 4 + rsub; r < nrows; r += 1024) {
        float4 v = x[(long)r * 64 + c4];
        s0 += v.x; q0 += v.x * v.x;
        s1 += v.y; q1 += v.y * v.y;
        s2 += v.z; q2 += v.z * v.z;
        s3 += v.w; q3 += v.w * v.w;
    }
    int col = c4 * 4;
    atomicAdd(&g_csum[slot][col + 0], s0);
    atomicAdd(&g_csum[slot][col + 1], s1);
    atomicAdd(&g_csum[slot][col + 2], s2);
    atomicAdd(&g_csum[slot][col + 3], s3);
    atomicAdd(&g_csq[slot][col + 0], q0);
    atomicAdd(&g_csq[slot][col + 1], q1);
    atomicAdd(&g_csq[slot][col + 2], q2);
    atomicAdd(&g_csq[slot][col + 3], q3);
}
__global__ void k_colstats2() {  // GCN: g_h halves -> slots 0,1
    int grp = blockIdx.x >> 8;
    int blk = blockIdx.x & 255;
    colstats_body(grp ? (g_h + NAB * FDIM) : g_h, grp ? NAG : NAB, grp, blk);
}
__global__ void k_bn_relu2(const float* __restrict__ g_ab, const float* __restrict__ be_ab,
                           const float* __restrict__ g_ag, const float* __restrict__ be_ag) {
    int idx = blockIdx.x * blockDim.x + threadIdx.x;
    if (idx >= NTOT * 64) return;
    int row = idx >> 6;
    int slot = (row < NAB) ? 0 : 1;
    float n = (float)(slot ? NAG : NAB);
    const float* g = slot ? g_ag : g_ab;
    const float* be = slot ? be_ag : be_ab;
    int f = (idx & 63) << 2;
    float4 v = *((float4*)g_h + idx);
    float* pv = &v.x;
#pragma unroll
    for (int j = 0; j < 4; j++) {
        float mu = g_csum[slot][f + j] / n;
        float var = g_csq[slot][f + j] / n - mu * mu;
        float o = (pv[j] - mu) * rsqrtf(var + EPSV) * g[f + j] + be[f + j];
        pv[j] = o > 0.f ? o : 0.f;
    }
    *((float4*)g_h + idx) = v;
}
// head stats for g_h halves -> slots 2,3; blocks 0,1 zero slots 0,1 first
__global__ void k_colstats_h() {
    int grp = blockIdx.x >> 8;
    int blk = blockIdx.x & 255;
    if (blockIdx.x < 2) {
        g_csum[blockIdx.x][threadIdx.x] = 0.f;
        g_csq[blockIdx.x][threadIdx.x] = 0.f;
    }
    colstats_body(grp ? (g_h + NAB * FDIM) : g_h, grp ? NAG : NAB, 2 + grp, blk);
}
// head stats for g_xb halves -> slots 0,1
__global__ void k_colstats_x() {
    int grp = blockIdx.x >> 8;
    int blk = blockIdx.x & 255;
    colstats_body(grp ? (g_xb + NAB * FDIM) : g_xb, grp ? NAG : NAB, grp, blk);
}

// ---------------- GAT ----------------
__global__ void k_dots(const float* __restrict__ a_s, const float* __restrict__ a_d) {
    int w = (blockIdx.x * blockDim.x + threadIdx.x) >> 5;
    int lane = threadIdx.x & 31;
    if (w >= NTOT) return;
    const float4* hp = (const float4*)(g_tmp + (long)w * FDIM);
    const float4* ap = (const float4*)a_s;
    const float4* dp = (const float4*)a_d;
    float s = 0.f, d = 0.f;
#pragma unroll
    for (int c = 0; c < 2; c++) {
        float4 hv = hp[lane + c * 32];
        float4 av = ap[lane + c * 32];
        float4 dv = dp[lane + c * 32];
        s += hv.x * av.x + hv.y * av.y + hv.z * av.z + hv.w * av.w;
        d += hv.x * dv.x + hv.y * dv.y + hv.z * dv.z + hv.w * dv.w;
    }
#pragma unroll
    for (int o = 16; o; o >>= 1) {
        s += __shfl_xor_sync(0xFFFFFFFFu, s, o);
        d += __shfl_xor_sync(0xFFFFFFFFu, d, o);
    }
    if (lane == 0) {
        g_es[w] = s;
        g_ed[w] = d;
    }
}
__global__ void k_gat_pull(int accwhich, const float* __restrict__ b, int dorelu) {
    int w = (blockIdx.x * blockDim.x + threadIdx.x) >> 5;
    int lane = threadIdx.x & 31;
    if (w >= NTOT) return;
    int rb = 2 * NTOT;
    int r0 = g_rowg[rb + w], r1 = g_rowg[rb + w + 1];
    float edd = g_ed[w];
    float eself = lrelu(g_es[w] + edd);
    float m = eself;
    for (int j = r0 + lane; j < r1; j += 32) {
        m = fmaxf(m, lrelu(g_es[g_srt[j]] + edd));
    }
#pragma unroll
    for (int o = 16; o; o >>= 1) m = fmaxf(m, __shfl_xor_sync(0xFFFFFFFFu, m, o));
    float exs = __expf(eself - m);
    float ssum = exs;
    const float4* hp = (const float4*)(g_tmp + (long)w * FDIM);
    float4 a0 = hp[lane];
    float4 a1 = hp[lane + 32];
    a0.x *= exs; a0.y *= exs; a0.z *= exs; a0.w *= exs;
    a1.x *= exs; a1.y *= exs; a1.z *= exs; a1.w *= exs;
    for (int j = r0; j < r1; j++) {
        int s = g_srt[j];
        float ex = __expf(lrelu(g_es[s] + edd) - m);
        ssum += ex;
        const float4* sp = (const float4*)(g_tmp + (long)s * FDIM);
        float4 v0 = sp[lane];
        float4 v1 = sp[lane + 32];
        a0.x += v0.x * ex; a0.y += v0.y * ex; a0.z += v0.z * ex; a0.w += v0.w * ex;
        a1.x += v1.x * ex; a1.y += v1.y * ex; a1.z += v1.z * ex; a1.w += v1.w * ex;
    }
    float inv = 1.0f / ssum;
    float4 b0 = *((const float4*)b + lane);
    float4 b1 = *((const float4*)b + lane + 32);
    a0.x = a0.x * inv + b0.x; a0.y = a0.y * inv + b0.y;
    a0.z = a0.z * inv + b0.z; a0.w = a0.w * inv + b0.w;
    a1.x = a1.x * inv + b1.x; a1.y = a1.y * inv + b1.y;
    a1.z = a1.z * inv + b1.z; a1.w = a1.w * inv + b1.w;
    if (dorelu) {
        a0.x = fmaxf(a0.x, 0.f); a0.y = fmaxf(a0.y, 0.f);
        a0.z = fmaxf(a0.z, 0.f); a0.w = fmaxf(a0.w, 0.f);
        a1.x = fmaxf(a1.x, 0.f); a1.y = fmaxf(a1.y, 0.f);
        a1.z = fmaxf(a1.z, 0.f); a1.w = fmaxf(a1.w, 0.f);
    }
    float4* op = (float4*)(BUF(accwhich) + (long)w * FDIM);
    op[lane] = a0;
    op[lane + 32] = a1;
}

// ---------------- final heads (grid = NTOT) ----------------
__global__ void k_head2(const float* __restrict__ g2, const float* __restrict__ be2,
                        const float* __restrict__ W_fc, const float* __restrict__ b_fc,
                        const float* __restrict__ ag_g2, const float* __restrict__ ag_be2,
                        const float* __restrict__ W_agfc, const float* __restrict__ b_agfc,
                        float* __restrict__ out) {
    __shared__ float red[8];
    int row = blockIdx.x;
    int t = threadIdx.x;
    int lane = t & 31, wid = t >> 5;
    const float *xpart, *hpart, *g, *be, *W, *b;
    int slot_x, slot_h, lrow;
    if (row < NAB) {
        lrow = row;
        xpart = g_xb; hpart = g_h;
        slot_x = 0; slot_h = 2;
        g = g2; be = be2; W = W_fc; b = b_fc;
    } else {
        lrow = row - NAB;
        xpart = g_xb + NAB * FDIM; hpart = g_h + NAB * FDIM;
        slot_x = 1; slot_h = 3;
        g = ag_g2; be = ag_be2; W = W_agfc; b = b_agfc;
    }
    float n = (float)NAB;  // NAB == NAG
    float mu1 = g_csum[slot_x][t] / n;
    float var1 = g_csq[slot_x][t] / n - mu1 * mu1;
    float v1 = (xpart[lrow * FDIM + t] - mu1) * rsqrtf(var1 + EPSV) * g[t] + be[t];
    v1 = v1 > 0.f ? v1 : 0.f;
    float mu2 = g_csum[slot_h][t] / n;
    float var2 = g_csq[slot_h][t] / n - mu2 * mu2;
    float v2 = (hpart[lrow * FDIM + t] - mu2) * rsqrtf(var2 + EPSV) * g[FDIM + t] + be[FDIM + t];
    v2 = v2 > 0.f ? v2 : 0.f;
    float p = v1 * W[t] + v2 * W[FDIM + t];
#pragma unroll
    for (int o = 16; o; o >>= 1) p += __shfl_xor_sync(0xFFFFFFFFu, p, o);
    if (lane == 0) red[wid] = p;
    __syncthreads();
    if (t == 0) {
        float acc = red[0];
#pragma unroll
        for (int i = 1; i < 8; i++) acc += red[i];
        out[row] = acc + b[0];
    }
}

// ---------------- host orchestration (launches + capture-legal fork/join) ----------------
extern "C" void kernel_launch(void* const* d_in, const int* in_sizes, int n_in, void* d_out,
                              int out_size) {
    const float* x_ab = (const float*)d_in[0];
    const float* x_ag = (const float*)d_in[1];
    const float* W_gcn = (const float*)d_in[2];
    const float* b_gcn = (const float*)d_in[3];
    const float* g1 = (const float*)d_in[4];
    const float* be1 = (const float*)d_in[5];
    const float* W_aggcn = (const float*)d_in[6];
    const float* b_aggcn = (const float*)d_in[7];
    const float* ag_g1 = (const float*)d_in[8];
    const float* ag_be1 = (const float*)d_in[9];
    const float* W_gat = (const float*)d_in[10];
    const float* a_src = (const float*)d_in[11];
    const float* a_dst = (const float*)d_in[12];
    const float* b_gat = (const float*)d_in[13];
    const float* W_gat2 = (const float*)d_in[14];
    const float* a_src2 = (const float*)d_in[15];
    const float* a_dst2 = (const float*)d_in[16];
    const float* b_gat2 = (const float*)d_in[17];
    const float* ag_g2 = (const float*)d_in[18];
    const float* ag_be2 = (const float*)d_in[19];
    const float* W_agfc = (const float*)d_in[20];
    const float* b_agfc = (const float*)d_in[21];
    const float* g2 = (const float*)d_in[22];
    const float* be2 = (const float*)d_in[23];
    const float* W_fc = (const float*)d_in[24];
    const float* b_fc = (const float*)d_in[25];
    const int* e_ab = (const int*)d_in[26];
    const int* e_ag = (const int*)d_in[27];
    const int* e_d = (const int*)d_in[28];
    float* out = (float*)d_out;

    cudaStream_t s2;
    cudaStreamCreateWithFlags(&s2, cudaStreamNonBlocking);
    cudaEvent_t evFork1, evJoin1, evFork2, evJoin2;
    cudaEventCreateWithFlags(&evFork1, cudaEventDisableTiming);
    cudaEventCreateWithFlags(&evJoin1, cudaEventDisableTiming);
    cudaEventCreateWithFlags(&evFork2, cudaEventDisableTiming);
    cudaEventCreateWithFlags(&evJoin2, cudaEventDisableTiming);

    // fork: CSR build on s2, GCN dual-GEMM on main (independent)
    cudaEventRecord(evFork1, 0);
    cudaStreamWaitEvent(s2, evFork1, 0);
    k_zero_csr<<<(CSRN + 255) / 256, 256, 0, s2>>>();
    k_hist_all<<<(ETOT + 255) / 256, 256, 0, s2>>>(e_ab + EAB, e_ag + EAG, e_d + ED);
    k_scan1<<<SCAN_BLOCKS, 1024, 0, s2>>>();
    k_scan2<<<1, 128, 0, s2>>>();
    k_scan3<<<SCAN_BLOCKS, 1024, 0, s2>>>();
    k_fill_all<<<(ETOT + 255) / 256, 256, 0, s2>>>(e_ab, e_ag, e_d);
    cudaEventRecord(evJoin1, s2);

    {
        dim3 gg(2, (NAB + 127) / 128, 2);
        k_gemm2<<<gg, 256>>>(x_ab, W_gcn, x_ag, W_aggcn);
    }
    cudaStreamWaitEvent(0, evJoin1, 0);  // join: pull needs CSR + GEMM

    k_gcn_pull2<<<(NTOT + 7) / 8, 256>>>(b_gcn, b_aggcn);
    k_colstats2<<<512, 256>>>();
    k_bn_relu2<<<(NTOT * 64 + 255) / 256, 256>>>(g1, be1, ag_g1, ag_be1);

    // fork: g_h head-stats (slots 2,3) + zero slots 0,1 on s2, under GAT phase
    cudaEventRecord(evFork2, 0);
    cudaStreamWaitEvent(s2, evFork2, 0);
    k_colstats_h<<<512, 256, 0, s2>>>();
    cudaEventRecord(evJoin2, s2);

    // GAT layer 1: g_h(0) -> g_xa(1), relu
    {
        dim3 gg(2, (NTOT + 127) / 128);
        k_gemm<<<gg, 256>>>(nullptr, 0, W_gat, NTOT);
        k_dots<<<(NTOT + 7) / 8, 256>>>(a_src, a_dst);
        k_gat_pull<<<(NTOT + 7) / 8, 256>>>(1, b_gat, 1);
    }
    // GAT layer 2: g_xa(1) -> g_xb(2), no relu
    {
        dim3 gg(2, (NTOT + 127) / 128);
        k_gemm<<<gg, 256>>>(nullptr, 1, W_gat2, NTOT);
        k_dots<<<(NTOT + 7) / 8, 256>>>(a_src2, a_dst2);
        k_gat_pull<<<(NTOT + 7) / 8, 256>>>(2, b_gat2, 0);
    }

    cudaStreamWaitEvent(0, evJoin2, 0);  // join: slots 0,1 zeroed; slots 2,3 ready
    k_colstats_x<<<512, 256>>>();
    k_head2<<<NTOT, 256>>>(g2, be2, W_fc, b_fc, ag_g2, ag_be2, W_agfc, b_agfc, out);

    cudaEventDestroy(evFork1);
    cudaEventDestroy(evJoin1);
    cudaEventDestroy(evFork2);
    cudaEventDestroy(evJoin2);
    cudaStreamDestroy(s2);
}